// round 11
// baseline (speedup 1.0000x reference)
#include <cuda_runtime.h>
#include <cuda_fp16.h>
#include <cstdint>

#define NB    8
#define CIN   128
#define SP    1600
#define NHEAD 8
#define HD    16

typedef unsigned long long u64;

#define ONESH2 0x3C003C00u   // f16x2 (1.0, 1.0)

// ---- packed f32x2 helpers ----
__device__ __forceinline__ u64 pack2(float lo, float hi) {
    u64 r; asm("mov.b64 %0,{%1,%2};" : "=l"(r) : "f"(lo), "f"(hi)); return r;
}
__device__ __forceinline__ float2 unpack2(u64 v) {
    float2 r; asm("mov.b64 {%0,%1},%2;" : "=f"(r.x), "=f"(r.y) : "l"(v)); return r;
}

// f16x2 word: first arg -> low 16 bits, second -> high 16 bits
__device__ __forceinline__ uint32_t f16x2_of(float lo, float hi) {
    uint32_t r;
    asm("cvt.rn.f16x2.f32 %0, %1, %2;" : "=r"(r) : "f"(hi), "f"(lo));
    return r;
}
__device__ __forceinline__ void f16x2_to_f32(uint32_t w, float& lo, float& hi) {
    asm("{ .reg .b16 l, h; mov.b32 {l, h}, %2; cvt.f32.f16 %0, l; cvt.f32.f16 %1, h; }"
        : "=f"(lo), "=f"(hi) : "r"(w));
}
__device__ __forceinline__ u64 packh2(float a, float b) {
    uint32_t hw = f16x2_of(a, b);
    float ha, hb;
    f16x2_to_f32(hw, ha, hb);
    uint32_t lw = f16x2_of(a - ha, b - hb);
    return (u64)hw | ((u64)lw << 32);
}
// vectorized exp2 on both fp16 halves
__device__ __forceinline__ uint32_t ex2h2(uint32_t w) {
    uint32_t r; asm("ex2.approx.f16x2 %0, %1;" : "=r"(r) : "r"(w)); return r;
}

// warp mma: D += A(f16 16x16) * B(f16 16x8), f32 accum
__device__ __forceinline__ void mmaf16(float* d, const uint32_t* a, uint32_t b0, uint32_t b1) {
    asm volatile("mma.sync.aligned.m16n8k16.row.col.f32.f16.f16.f32 "
        "{%0,%1,%2,%3},{%4,%5,%6,%7},{%8,%9},{%0,%1,%2,%3};"
        : "+f"(d[0]), "+f"(d[1]), "+f"(d[2]), "+f"(d[3])
        : "r"(a[0]), "r"(a[1]), "r"(a[2]), "r"(a[3]), "r"(b0), "r"(b1));
}

// Scratch:
__device__ u64      g_wpk[(size_t)384 * 64];            // w_qkv hi/lo [o][cpair]
__device__ u64      g_wopk[(size_t)128 * 64];           // w_o hi/lo [o][cpair]
__device__ u64      g_xpk[(size_t)NB * 64 * SP];        // x hi/lo [n][cpair][s]
__device__ uint32_t g_qpk[(size_t)64 * 8 * SP + 64];    // Q f16x2 [nh][dpair][s] (+pad)
__device__ u64      g_kp2[(size_t)64 * SP * 4];         // K frag words [nh][tok][4]
__device__ u64      g_vp2[(size_t)64 * 100 * 16 * 4];   // V frag words [nh][kt][dim][4]
__device__ u64      g_opk[(size_t)NB * 64 * SP];        // attn out hi/lo [n][cpair][s]

// ===================================================================
// Conversion kernels: fp32 -> fp16 hi/lo u64 words.
// ===================================================================
__global__ void conv_w(const float* __restrict__ W) {   // [384][128]
    int idx = blockIdx.x * 256 + threadIdx.x;
    if (idx >= 384 * 64) return;
    int o = idx >> 6, cp = idx & 63;
    g_wpk[idx] = packh2(W[o * CIN + 2 * cp], W[o * CIN + 2 * cp + 1]);
}

__global__ void conv_wo(const float* __restrict__ W) {  // [128][128]
    int idx = blockIdx.x * 256 + threadIdx.x;
    if (idx >= 128 * 64) return;
    int o = idx >> 6, cp = idx & 63;
    g_wopk[idx] = packh2(W[o * CIN + 2 * cp], W[o * CIN + 2 * cp + 1]);
}

__global__ void conv_x(const float* __restrict__ X) {   // [n][128][1600]
    int idx = blockIdx.x * 256 + threadIdx.x;
    if (idx >= NB * 64 * (SP / 4)) return;
    int s4 = idx % (SP / 4);
    int rest = idx / (SP / 4);
    int cp = rest & 63, n = rest >> 6;
    const float* x0 = X + ((size_t)n * CIN + 2 * cp) * SP + s4 * 4;
    const float* x1 = x0 + SP;
    float4 a = *(const float4*)x0;
    float4 b = *(const float4*)x1;
    u64* dst = g_xpk + ((size_t)n * 64 + cp) * SP + s4 * 4;
    dst[0] = packh2(a.x, b.x);
    dst[1] = packh2(a.y, b.y);
    dst[2] = packh2(a.z, b.z);
    dst[3] = packh2(a.w, b.w);
}

// ===================================================================
// QKV projection on fp16 mma (3-term hi/lo) + pack epilogue.
// ===================================================================
__global__ __launch_bounds__(128) void proj_qkv_mma(void) {
    __shared__ float Ys[64][68];

    const int n  = blockIdx.z;
    const int s0 = blockIdx.x * 64;
    const int o0 = blockIdx.y * 64;
    const int tid = threadIdx.x;
    const int warp = tid >> 5, lane = tid & 31;
    const int g = lane >> 2, t = lane & 3;

    const u64* Wp = g_wpk;
    const u64* Xp = g_xpk + (size_t)n * 64 * SP;

    float d[8][4];
    #pragma unroll
    for (int nb = 0; nb < 8; nb++)
        #pragma unroll
        for (int j = 0; j < 4; j++) d[nb][j] = 0.f;

    const int r1 = o0 + warp * 16 + g;
    const int r2 = r1 + 8;

    #pragma unroll
    for (int ks = 0; ks < 8; ks++) {
        const int cp0 = ks * 8;
        u64 wA0 = Wp[(size_t)r1 * 64 + cp0 + t];
        u64 wA1 = Wp[(size_t)r2 * 64 + cp0 + t];
        u64 wA2 = Wp[(size_t)r1 * 64 + cp0 + 4 + t];
        u64 wA3 = Wp[(size_t)r2 * 64 + cp0 + 4 + t];
        uint32_t ah[4] = {(uint32_t)wA0, (uint32_t)wA1, (uint32_t)wA2, (uint32_t)wA3};
        uint32_t al[4] = {(uint32_t)(wA0 >> 32), (uint32_t)(wA1 >> 32),
                          (uint32_t)(wA2 >> 32), (uint32_t)(wA3 >> 32)};

        const u64* xr0 = Xp + (size_t)(cp0 + t) * SP + s0 + g;
        const u64* xr1 = Xp + (size_t)(cp0 + 4 + t) * SP + s0 + g;
        #pragma unroll
        for (int nb = 0; nb < 8; nb++) {
            u64 x0 = xr0[nb * 8];
            u64 x1 = xr1[nb * 8];
            mmaf16(d[nb], ah, (uint32_t)x0, (uint32_t)x1);
            mmaf16(d[nb], ah, (uint32_t)(x0 >> 32), (uint32_t)(x1 >> 32));
            mmaf16(d[nb], al, (uint32_t)x0, (uint32_t)x1);
        }
    }

    #pragma unroll
    for (int nb = 0; nb < 8; nb++) {
        int ol = warp * 16;
        int sl = nb * 8 + 2 * t;
        Ys[ol + g][sl]     = d[nb][0];
        Ys[ol + g][sl + 1] = d[nb][1];
        Ys[ol + 8 + g][sl]     = d[nb][2];
        Ys[ol + 8 + g][sl + 1] = d[nb][3];
    }
    __syncthreads();

    // ---- pack epilogue: 128 threads, 4 o-pairs each ----
    const int tx = tid & 15, ty = tid >> 4;   // ty in 0..7
    const float qs = 0.25f * 1.4426950408889634f;

    #pragma unroll
    for (int p = 0; p < 4; p++) {
        int olo = ty * 8 + 2 * p;
        int o = o0 + olo;
        int hh = o / 48;
        int within = o - hh * 48;
        int nhI = n * 8 + hh;
        float r0[4], r1[4];
        #pragma unroll
        for (int j = 0; j < 4; j++) {
            r0[j] = Ys[olo][tx * 4 + j];
            r1[j] = Ys[olo + 1][tx * 4 + j];
        }
        int tok0 = s0 + tx * 4;
        if (within < 16) {
            int dp = within >> 1;
            uint32_t* dst = g_qpk + ((size_t)nhI * 8 + dp) * SP + tok0;
            #pragma unroll
            for (int j = 0; j < 4; j++)
                dst[j] = f16x2_of(r0[j] * qs, r1[j] * qs);
        } else if (within < 32) {
            int dp = (within - 16) >> 1;
            uint32_t* kb = (uint32_t*)g_kp2 + (size_t)nhI * SP * 8;
            int off = (dp & 3) * 2 + (dp >> 2);
            #pragma unroll
            for (int j = 0; j < 4; j++)
                kb[(size_t)(tok0 + j) * 8 + off] = f16x2_of(r0[j], r1[j]);
        } else {
            int dl = within - 32;
            uint32_t* vb = (uint32_t*)g_vp2 + (size_t)nhI * 100 * 128;
            int kt  = tok0 >> 4;
            int kpl = (tok0 >> 1) & 7;
            size_t base = (size_t)kt * 128;
            vb[base + ((size_t)dl * 4 + (kpl & 3)) * 2 + (kpl >> 2)]             = f16x2_of(r0[0], r0[1]);
            vb[base + ((size_t)dl * 4 + ((kpl + 1) & 3)) * 2 + ((kpl + 1) >> 2)] = f16x2_of(r0[2], r0[3]);
            vb[base + ((size_t)(dl + 1) * 4 + (kpl & 3)) * 2 + (kpl >> 2)]             = f16x2_of(r1[0], r1[1]);
            vb[base + ((size_t)(dl + 1) * 4 + ((kpl + 1) & 3)) * 2 + ((kpl + 1) >> 2)] = f16x2_of(r1[2], r1[3]);
        }
    }
}

// ===================================================================
// Output projection on fp16 mma (3-term hi/lo) + bias epilogue.
// ===================================================================
__global__ __launch_bounds__(128) void proj_out_mma(const float* __restrict__ bias,
                                                    float* __restrict__ Y) {
    __shared__ float Ys[64][68];

    const int n  = blockIdx.z;
    const int s0 = blockIdx.x * 64;
    const int o0 = blockIdx.y * 64;
    const int tid = threadIdx.x;
    const int warp = tid >> 5, lane = tid & 31;
    const int g = lane >> 2, t = lane & 3;

    const u64* Wp = g_wopk;
    const u64* Xp = g_opk + (size_t)n * 64 * SP;

    float d[8][4];
    #pragma unroll
    for (int nb = 0; nb < 8; nb++)
        #pragma unroll
        for (int j = 0; j < 4; j++) d[nb][j] = 0.f;

    const int r1 = o0 + warp * 16 + g;
    const int r2 = r1 + 8;

    #pragma unroll
    for (int ks = 0; ks < 8; ks++) {
        const int cp0 = ks * 8;
        u64 wA0 = Wp[(size_t)r1 * 64 + cp0 + t];
        u64 wA1 = Wp[(size_t)r2 * 64 + cp0 + t];
        u64 wA2 = Wp[(size_t)r1 * 64 + cp0 + 4 + t];
        u64 wA3 = Wp[(size_t)r2 * 64 + cp0 + 4 + t];
        uint32_t ah[4] = {(uint32_t)wA0, (uint32_t)wA1, (uint32_t)wA2, (uint32_t)wA3};
        uint32_t al[4] = {(uint32_t)(wA0 >> 32), (uint32_t)(wA1 >> 32),
                          (uint32_t)(wA2 >> 32), (uint32_t)(wA3 >> 32)};

        const u64* xr0 = Xp + (size_t)(cp0 + t) * SP + s0 + g;
        const u64* xr1 = Xp + (size_t)(cp0 + 4 + t) * SP + s0 + g;
        #pragma unroll
        for (int nb = 0; nb < 8; nb++) {
            u64 x0 = xr0[nb * 8];
            u64 x1 = xr1[nb * 8];
            mmaf16(d[nb], ah, (uint32_t)x0, (uint32_t)x1);
            mmaf16(d[nb], ah, (uint32_t)(x0 >> 32), (uint32_t)(x1 >> 32));
            mmaf16(d[nb], al, (uint32_t)x0, (uint32_t)x1);
        }
    }

    #pragma unroll
    for (int nb = 0; nb < 8; nb++) {
        int ol = warp * 16;
        int sl = nb * 8 + 2 * t;
        Ys[ol + g][sl]     = d[nb][0];
        Ys[ol + g][sl + 1] = d[nb][1];
        Ys[ol + 8 + g][sl]     = d[nb][2];
        Ys[ol + 8 + g][sl + 1] = d[nb][3];
    }
    __syncthreads();

    // ---- bias + store epilogue ----
    const int tx = tid & 15, ty = tid >> 4;
    #pragma unroll
    for (int r = 0; r < 8; r++) {
        int olo = ty * 8 + r;
        int o = o0 + olo;
        float b = bias[o];
        float4 v = *(const float4*)&Ys[olo][tx * 4];
        v.x += b; v.y += b; v.z += b; v.w += b;
        *(float4*)(Y + ((size_t)n * CIN + o) * SP + s0 + tx * 4) = v;
    }
}

// ===================================================================
// Attention: 32 q/warp, f16x2 exp, l via ones-MMA, depth-1 prefetch.
// ===================================================================
__global__ __launch_bounds__(128) void attn_mma(void) {
    const int tid  = threadIdx.x;
    const int warp = tid >> 5, lane = tid & 31;
    const int g = lane >> 2, t = lane & 3;
    const int nh = blockIdx.y, n = nh >> 3, h = nh & 7;
    const int q0 = blockIdx.x * 128 + warp * 32;

    const uint32_t* qp = g_qpk + (size_t)nh * 8 * SP;
    const u64* kp2 = g_kp2 + (size_t)nh * SP * 4;
    const u64* vp2 = g_vp2 + (size_t)nh * 100 * 64;

    uint32_t aq0[4], aq1[4];
    {
        const uint32_t* q1 = qp + (size_t)t * SP;
        const uint32_t* q2 = qp + (size_t)(t + 4) * SP;
        aq0[0] = q1[q0 + g];      aq0[1] = q1[q0 + 8 + g];
        aq0[2] = q2[q0 + g];      aq0[3] = q2[q0 + 8 + g];
        aq1[0] = q1[q0 + 16 + g]; aq1[1] = q1[q0 + 24 + g];
        aq1[2] = q2[q0 + 16 + g]; aq1[3] = q2[q0 + 24 + g];
    }

    float dA0[4] = {0,0,0,0}, dA1[4] = {0,0,0,0};
    float dB0[4] = {0,0,0,0}, dB1[4] = {0,0,0,0};
    float dLA[4] = {0,0,0,0}, dLB[4] = {0,0,0,0};

    const u64* kA_p = kp2 + (size_t)g * 4 + t;
    const u64* kB_p = kp2 + (size_t)(8 + g) * 4 + t;
    const u64* vA_p = vp2 + (size_t)g * 4 + t;
    const u64* vB_p = vp2 + (size_t)(8 + g) * 4 + t;

    // prologue: load tile 0
    u64 kA = kA_p[0], kB = kB_p[0], vA = vA_p[0], vB = vB_p[0];

    #pragma unroll 2
    for (int kt = 0; kt < 100; kt++) {
        // ---- depth-1 prefetch of next tile (clamped on last iter)
        size_t nx = (size_t)(kt + (kt < 99)) * 64;
        u64 nkA = kA_p[nx], nkB = kB_p[nx];
        u64 nvA = vA_p[nx], nvB = vB_p[nx];

        float s00[4] = {0,0,0,0}, s01[4] = {0,0,0,0};
        float s10[4] = {0,0,0,0}, s11[4] = {0,0,0,0};
        mmaf16(s00, aq0, (uint32_t)kA, (uint32_t)(kA >> 32));
        mmaf16(s01, aq0, (uint32_t)kB, (uint32_t)(kB >> 32));
        mmaf16(s10, aq1, (uint32_t)kA, (uint32_t)(kA >> 32));
        mmaf16(s11, aq1, (uint32_t)kB, (uint32_t)(kB >> 32));

        uint32_t paA[4], paB[4];
        paA[0] = ex2h2(f16x2_of(s00[0], s00[1]));
        paA[1] = ex2h2(f16x2_of(s00[2], s00[3]));
        paA[2] = ex2h2(f16x2_of(s01[0], s01[1]));
        paA[3] = ex2h2(f16x2_of(s01[2], s01[3]));
        paB[0] = ex2h2(f16x2_of(s10[0], s10[1]));
        paB[1] = ex2h2(f16x2_of(s10[2], s10[3]));
        paB[2] = ex2h2(f16x2_of(s11[0], s11[1]));
        paB[3] = ex2h2(f16x2_of(s11[2], s11[3]));

        mmaf16(dLA, paA, ONESH2, ONESH2);
        mmaf16(dLB, paB, ONESH2, ONESH2);

        mmaf16(dA0, paA, (uint32_t)vA, (uint32_t)(vA >> 32));
        mmaf16(dA1, paA, (uint32_t)vB, (uint32_t)(vB >> 32));
        mmaf16(dB0, paB, (uint32_t)vA, (uint32_t)(vA >> 32));
        mmaf16(dB1, paB, (uint32_t)vB, (uint32_t)(vB >> 32));

        kA = nkA; kB = nkB; vA = nvA; vB = nvB;
    }

    // ---- packed hi/lo output: [n][cpair][s]
    u64* op = g_opk + (size_t)n * 64 * SP;
    const int cp0 = h * 8 + t;
    const int cp1 = h * 8 + 4 + t;

    #pragma unroll
    for (int tile = 0; tile < 2; tile++) {
        int qb = q0 + tile * 16;
        const float* d0 = tile ? dB0 : dA0;
        const float* d1 = tile ? dB1 : dA1;
        const float* dL = tile ? dLB : dLA;
        float i0 = 1.f / dL[0];
        float i1 = 1.f / dL[2];
        if (qb + g < SP) {
            op[(size_t)cp0 * SP + qb + g] = packh2(d0[0] * i0, d0[1] * i0);
            op[(size_t)cp1 * SP + qb + g] = packh2(d1[0] * i0, d1[1] * i0);
        }
        if (qb + 8 + g < SP) {
            op[(size_t)cp0 * SP + qb + 8 + g] = packh2(d0[2] * i1, d0[3] * i1);
            op[(size_t)cp1 * SP + qb + 8 + g] = packh2(d1[2] * i1, d1[3] * i1);
        }
    }
}

// ===================================================================
extern "C" void kernel_launch(void* const* d_in, const int* in_sizes, int n_in,
                              void* d_out, int out_size) {
    const float* x     = (const float*)d_in[0];
    const float* w_qkv = (const float*)d_in[1];
    const float* w_o   = (const float*)d_in[2];
    const float* b_o   = (const float*)d_in[3];
    float* out = (float*)d_out;

    conv_w<<<(384 * 64 + 255) / 256, 256>>>(w_qkv);
    conv_wo<<<(128 * 64 + 255) / 256, 256>>>(w_o);
    conv_x<<<(NB * 64 * (SP / 4) + 255) / 256, 256>>>(x);
    proj_qkv_mma<<<dim3(SP / 64, 384 / 64, NB), 128>>>();
    attn_mma<<<dim3(13, NB * NHEAD), 128>>>();
    proj_out_mma<<<dim3(SP / 64, CIN / 64, NB), 128>>>(b_o, out);
}

// round 12
// speedup vs baseline: 1.0287x; 1.0287x over previous
#include <cuda_runtime.h>
#include <cuda_fp16.h>
#include <cstdint>

#define NB    8
#define CIN   128
#define SP    1600
#define NHEAD 8
#define HD    16

typedef unsigned long long u64;

#define ONESH2 0x3C003C00u   // f16x2 (1.0, 1.0)

// f16x2 word: first arg -> low 16 bits, second -> high 16 bits
__device__ __forceinline__ uint32_t f16x2_of(float lo, float hi) {
    uint32_t r;
    asm("cvt.rn.f16x2.f32 %0, %1, %2;" : "=r"(r) : "f"(hi), "f"(lo));
    return r;
}
__device__ __forceinline__ void f16x2_to_f32(uint32_t w, float& lo, float& hi) {
    asm("{ .reg .b16 l, h; mov.b32 {l, h}, %2; cvt.f32.f16 %0, l; cvt.f32.f16 %1, h; }"
        : "=f"(lo), "=f"(hi) : "r"(w));
}
__device__ __forceinline__ u64 packh2(float a, float b) {
    uint32_t hw = f16x2_of(a, b);
    float ha, hb;
    f16x2_to_f32(hw, ha, hb);
    uint32_t lw = f16x2_of(a - ha, b - hb);
    return (u64)hw | ((u64)lw << 32);
}
__device__ __forceinline__ uint32_t ex2h2(uint32_t w) {
    uint32_t r; asm("ex2.approx.f16x2 %0, %1;" : "=r"(r) : "r"(w)); return r;
}

// warp mma: D += A(f16 16x16) * B(f16 16x8), f32 accum
__device__ __forceinline__ void mmaf16(float* d, const uint32_t* a, uint32_t b0, uint32_t b1) {
    asm volatile("mma.sync.aligned.m16n8k16.row.col.f32.f16.f16.f32 "
        "{%0,%1,%2,%3},{%4,%5,%6,%7},{%8,%9},{%0,%1,%2,%3};"
        : "+f"(d[0]), "+f"(d[1]), "+f"(d[2]), "+f"(d[3])
        : "r"(a[0]), "r"(a[1]), "r"(a[2]), "r"(a[3]), "r"(b0), "r"(b1));
}

// Scratch:
__device__ u64      g_wpk[(size_t)384 * 64];            // w_qkv hi/lo [o][cpair]
__device__ u64      g_wopk[(size_t)128 * 64];           // w_o hi/lo [o][cpair]
__device__ u64      g_xpk[(size_t)NB * 64 * SP];        // x hi/lo [n][cpair][s]
__device__ uint32_t g_qpk[(size_t)64 * 8 * SP + 64];    // Q f16x2 [nh][dpair][s] (+pad)
__device__ u64      g_kp2[(size_t)64 * SP * 4];         // K frag words [nh][tok][4]
__device__ u64      g_vp2[(size_t)64 * 100 * 16 * 4];   // V frag words [nh][kt][dim][4]
__device__ float2   g_pnum[(size_t)2 * 64 * 8 * SP];    // partial numerators [z][nh][cp][s]
__device__ float    g_pden[(size_t)2 * 64 * SP];        // partial denominators [z][nh][s]
__device__ u64      g_opk[(size_t)NB * 64 * SP];        // attn out hi/lo [n][cpair][s]

// ===================================================================
// Conversion kernels
// ===================================================================
__global__ void conv_w(const float* __restrict__ W) {
    int idx = blockIdx.x * 256 + threadIdx.x;
    if (idx >= 384 * 64) return;
    int o = idx >> 6, cp = idx & 63;
    g_wpk[idx] = packh2(W[o * CIN + 2 * cp], W[o * CIN + 2 * cp + 1]);
}

__global__ void conv_wo(const float* __restrict__ W) {
    int idx = blockIdx.x * 256 + threadIdx.x;
    if (idx >= 128 * 64) return;
    int o = idx >> 6, cp = idx & 63;
    g_wopk[idx] = packh2(W[o * CIN + 2 * cp], W[o * CIN + 2 * cp + 1]);
}

__global__ void conv_x(const float* __restrict__ X) {
    int idx = blockIdx.x * 256 + threadIdx.x;
    if (idx >= NB * 64 * (SP / 4)) return;
    int s4 = idx % (SP / 4);
    int rest = idx / (SP / 4);
    int cp = rest & 63, n = rest >> 6;
    const float* x0 = X + ((size_t)n * CIN + 2 * cp) * SP + s4 * 4;
    const float* x1 = x0 + SP;
    float4 a = *(const float4*)x0;
    float4 b = *(const float4*)x1;
    u64* dst = g_xpk + ((size_t)n * 64 + cp) * SP + s4 * 4;
    dst[0] = packh2(a.x, b.x);
    dst[1] = packh2(a.y, b.y);
    dst[2] = packh2(a.z, b.z);
    dst[3] = packh2(a.w, b.w);
}

// ===================================================================
// QKV projection on fp16 mma (3-term hi/lo) + pack epilogue.
// ===================================================================
__global__ __launch_bounds__(128) void proj_qkv_mma(void) {
    __shared__ float Ys[64][68];

    const int n  = blockIdx.z;
    const int s0 = blockIdx.x * 64;
    const int o0 = blockIdx.y * 64;
    const int tid = threadIdx.x;
    const int warp = tid >> 5, lane = tid & 31;
    const int g = lane >> 2, t = lane & 3;

    const u64* Wp = g_wpk;
    const u64* Xp = g_xpk + (size_t)n * 64 * SP;

    float d[8][4];
    #pragma unroll
    for (int nb = 0; nb < 8; nb++)
        #pragma unroll
        for (int j = 0; j < 4; j++) d[nb][j] = 0.f;

    const int r1 = o0 + warp * 16 + g;
    const int r2 = r1 + 8;

    #pragma unroll
    for (int ks = 0; ks < 8; ks++) {
        const int cp0 = ks * 8;
        u64 wA0 = Wp[(size_t)r1 * 64 + cp0 + t];
        u64 wA1 = Wp[(size_t)r2 * 64 + cp0 + t];
        u64 wA2 = Wp[(size_t)r1 * 64 + cp0 + 4 + t];
        u64 wA3 = Wp[(size_t)r2 * 64 + cp0 + 4 + t];
        uint32_t ah[4] = {(uint32_t)wA0, (uint32_t)wA1, (uint32_t)wA2, (uint32_t)wA3};
        uint32_t al[4] = {(uint32_t)(wA0 >> 32), (uint32_t)(wA1 >> 32),
                          (uint32_t)(wA2 >> 32), (uint32_t)(wA3 >> 32)};

        const u64* xr0 = Xp + (size_t)(cp0 + t) * SP + s0 + g;
        const u64* xr1 = Xp + (size_t)(cp0 + 4 + t) * SP + s0 + g;
        #pragma unroll
        for (int nb = 0; nb < 8; nb++) {
            u64 x0 = xr0[nb * 8];
            u64 x1 = xr1[nb * 8];
            mmaf16(d[nb], ah, (uint32_t)x0, (uint32_t)x1);
            mmaf16(d[nb], ah, (uint32_t)(x0 >> 32), (uint32_t)(x1 >> 32));
            mmaf16(d[nb], al, (uint32_t)x0, (uint32_t)x1);
        }
    }

    #pragma unroll
    for (int nb = 0; nb < 8; nb++) {
        int ol = warp * 16;
        int sl = nb * 8 + 2 * t;
        Ys[ol + g][sl]     = d[nb][0];
        Ys[ol + g][sl + 1] = d[nb][1];
        Ys[ol + 8 + g][sl]     = d[nb][2];
        Ys[ol + 8 + g][sl + 1] = d[nb][3];
    }
    __syncthreads();

    // ---- pack epilogue: 128 threads, 4 o-pairs each ----
    const int tx = tid & 15, ty = tid >> 4;   // ty in 0..7
    const float qs = 0.25f * 1.4426950408889634f;

    #pragma unroll
    for (int p = 0; p < 4; p++) {
        int olo = ty * 8 + 2 * p;
        int o = o0 + olo;
        int hh = o / 48;
        int within = o - hh * 48;
        int nhI = n * 8 + hh;
        float r0[4], r1[4];
        #pragma unroll
        for (int j = 0; j < 4; j++) {
            r0[j] = Ys[olo][tx * 4 + j];
            r1[j] = Ys[olo + 1][tx * 4 + j];
        }
        int tok0 = s0 + tx * 4;
        if (within < 16) {
            int dp = within >> 1;
            uint32_t* dst = g_qpk + ((size_t)nhI * 8 + dp) * SP + tok0;
            #pragma unroll
            for (int j = 0; j < 4; j++)
                dst[j] = f16x2_of(r0[j] * qs, r1[j] * qs);
        } else if (within < 32) {
            int dp = (within - 16) >> 1;
            uint32_t* kb = (uint32_t*)g_kp2 + (size_t)nhI * SP * 8;
            int off = (dp & 3) * 2 + (dp >> 2);
            #pragma unroll
            for (int j = 0; j < 4; j++)
                kb[(size_t)(tok0 + j) * 8 + off] = f16x2_of(r0[j], r1[j]);
        } else {
            int dl = within - 32;
            uint32_t* vb = (uint32_t*)g_vp2 + (size_t)nhI * 100 * 128;
            int kt  = tok0 >> 4;
            int kpl = (tok0 >> 1) & 7;
            size_t base = (size_t)kt * 128;
            vb[base + ((size_t)dl * 4 + (kpl & 3)) * 2 + (kpl >> 2)]             = f16x2_of(r0[0], r0[1]);
            vb[base + ((size_t)dl * 4 + ((kpl + 1) & 3)) * 2 + ((kpl + 1) >> 2)] = f16x2_of(r0[2], r0[3]);
            vb[base + ((size_t)(dl + 1) * 4 + (kpl & 3)) * 2 + (kpl >> 2)]             = f16x2_of(r1[0], r1[1]);
            vb[base + ((size_t)(dl + 1) * 4 + ((kpl + 1) & 3)) * 2 + ((kpl + 1) >> 2)] = f16x2_of(r1[2], r1[3]);
        }
    }
}

// ===================================================================
// Output projection on fp16 mma (3-term hi/lo) + bias epilogue.
// ===================================================================
__global__ __launch_bounds__(128) void proj_out_mma(const float* __restrict__ bias,
                                                    float* __restrict__ Y) {
    __shared__ float Ys[64][68];

    const int n  = blockIdx.z;
    const int s0 = blockIdx.x * 64;
    const int o0 = blockIdx.y * 64;
    const int tid = threadIdx.x;
    const int warp = tid >> 5, lane = tid & 31;
    const int g = lane >> 2, t = lane & 3;

    const u64* Wp = g_wopk;
    const u64* Xp = g_opk + (size_t)n * 64 * SP;

    float d[8][4];
    #pragma unroll
    for (int nb = 0; nb < 8; nb++)
        #pragma unroll
        for (int j = 0; j < 4; j++) d[nb][j] = 0.f;

    const int r1 = o0 + warp * 16 + g;
    const int r2 = r1 + 8;

    #pragma unroll
    for (int ks = 0; ks < 8; ks++) {
        const int cp0 = ks * 8;
        u64 wA0 = Wp[(size_t)r1 * 64 + cp0 + t];
        u64 wA1 = Wp[(size_t)r2 * 64 + cp0 + t];
        u64 wA2 = Wp[(size_t)r1 * 64 + cp0 + 4 + t];
        u64 wA3 = Wp[(size_t)r2 * 64 + cp0 + 4 + t];
        uint32_t ah[4] = {(uint32_t)wA0, (uint32_t)wA1, (uint32_t)wA2, (uint32_t)wA3};
        uint32_t al[4] = {(uint32_t)(wA0 >> 32), (uint32_t)(wA1 >> 32),
                          (uint32_t)(wA2 >> 32), (uint32_t)(wA3 >> 32)};

        const u64* xr0 = Xp + (size_t)(cp0 + t) * SP + s0 + g;
        const u64* xr1 = Xp + (size_t)(cp0 + 4 + t) * SP + s0 + g;
        #pragma unroll
        for (int nb = 0; nb < 8; nb++) {
            u64 x0 = xr0[nb * 8];
            u64 x1 = xr1[nb * 8];
            mmaf16(d[nb], ah, (uint32_t)x0, (uint32_t)x1);
            mmaf16(d[nb], ah, (uint32_t)(x0 >> 32), (uint32_t)(x1 >> 32));
            mmaf16(d[nb], al, (uint32_t)x0, (uint32_t)x1);
        }
    }

    #pragma unroll
    for (int nb = 0; nb < 8; nb++) {
        int ol = warp * 16;
        int sl = nb * 8 + 2 * t;
        Ys[ol + g][sl]     = d[nb][0];
        Ys[ol + g][sl + 1] = d[nb][1];
        Ys[ol + 8 + g][sl]     = d[nb][2];
        Ys[ol + 8 + g][sl + 1] = d[nb][3];
    }
    __syncthreads();

    const int tx = tid & 15, ty = tid >> 4;
    #pragma unroll
    for (int r = 0; r < 8; r++) {
        int olo = ty * 8 + r;
        int o = o0 + olo;
        float b = bias[o];
        float4 v = *(const float4*)&Ys[olo][tx * 4];
        v.x += b; v.y += b; v.z += b; v.w += b;
        *(float4*)(Y + ((size_t)n * CIN + o) * SP + s0 + tx * 4) = v;
    }
}

// ===================================================================
// Attention, key-split: blockIdx.z selects key half (50 tiles each).
// Emits fp32 partial numerators + denominators.
// ===================================================================
__global__ __launch_bounds__(128) void attn_mma(void) {
    const int tid  = threadIdx.x;
    const int warp = tid >> 5, lane = tid & 31;
    const int g = lane >> 2, t = lane & 3;
    const int nh = blockIdx.y;
    const int z  = blockIdx.z;
    const int q0 = blockIdx.x * 128 + warp * 32;

    const uint32_t* qp = g_qpk + (size_t)nh * 8 * SP;
    const u64* kp2 = g_kp2 + (size_t)nh * SP * 4;
    const u64* vp2 = g_vp2 + (size_t)nh * 100 * 64;

    uint32_t aq0[4], aq1[4];
    {
        const uint32_t* q1 = qp + (size_t)t * SP;
        const uint32_t* q2 = qp + (size_t)(t + 4) * SP;
        aq0[0] = q1[q0 + g];      aq0[1] = q1[q0 + 8 + g];
        aq0[2] = q2[q0 + g];      aq0[3] = q2[q0 + 8 + g];
        aq1[0] = q1[q0 + 16 + g]; aq1[1] = q1[q0 + 24 + g];
        aq1[2] = q2[q0 + 16 + g]; aq1[3] = q2[q0 + 24 + g];
    }

    float dA0[4] = {0,0,0,0}, dA1[4] = {0,0,0,0};
    float dB0[4] = {0,0,0,0}, dB1[4] = {0,0,0,0};
    float dLA[4] = {0,0,0,0}, dLB[4] = {0,0,0,0};

    const u64* kA_p = kp2 + (size_t)g * 4 + t;
    const u64* kB_p = kp2 + (size_t)(8 + g) * 4 + t;
    const u64* vA_p = vp2 + (size_t)g * 4 + t;
    const u64* vB_p = vp2 + (size_t)(8 + g) * 4 + t;

    const int kt0 = z * 50, kt1 = kt0 + 50;

    #pragma unroll 2
    for (int kt = kt0; kt < kt1; kt++) {
        u64 kA = kA_p[(size_t)kt * 64];
        u64 kB = kB_p[(size_t)kt * 64];

        float s00[4] = {0,0,0,0}, s01[4] = {0,0,0,0};
        float s10[4] = {0,0,0,0}, s11[4] = {0,0,0,0};
        mmaf16(s00, aq0, (uint32_t)kA, (uint32_t)(kA >> 32));
        mmaf16(s01, aq0, (uint32_t)kB, (uint32_t)(kB >> 32));
        mmaf16(s10, aq1, (uint32_t)kA, (uint32_t)(kA >> 32));
        mmaf16(s11, aq1, (uint32_t)kB, (uint32_t)(kB >> 32));

        uint32_t paA[4], paB[4];
        paA[0] = ex2h2(f16x2_of(s00[0], s00[1]));
        paA[1] = ex2h2(f16x2_of(s00[2], s00[3]));
        paA[2] = ex2h2(f16x2_of(s01[0], s01[1]));
        paA[3] = ex2h2(f16x2_of(s01[2], s01[3]));
        paB[0] = ex2h2(f16x2_of(s10[0], s10[1]));
        paB[1] = ex2h2(f16x2_of(s10[2], s10[3]));
        paB[2] = ex2h2(f16x2_of(s11[0], s11[1]));
        paB[3] = ex2h2(f16x2_of(s11[2], s11[3]));

        mmaf16(dLA, paA, ONESH2, ONESH2);
        mmaf16(dLB, paB, ONESH2, ONESH2);

        u64 vA = vA_p[(size_t)kt * 64];
        u64 vB = vB_p[(size_t)kt * 64];
        mmaf16(dA0, paA, (uint32_t)vA, (uint32_t)(vA >> 32));
        mmaf16(dA1, paA, (uint32_t)vB, (uint32_t)(vB >> 32));
        mmaf16(dB0, paB, (uint32_t)vA, (uint32_t)(vA >> 32));
        mmaf16(dB1, paB, (uint32_t)vB, (uint32_t)(vB >> 32));
    }

    // ---- partial stores: numerators per (cp, s); denominator per s
    float2* pn = g_pnum + ((size_t)(z * 64 + nh) * 8) * SP;
    float*  pd = g_pden + (size_t)(z * 64 + nh) * SP;

    #pragma unroll
    for (int tile = 0; tile < 2; tile++) {
        int qb = q0 + tile * 16;
        const float* d0 = tile ? dB0 : dA0;
        const float* d1 = tile ? dB1 : dA1;
        const float* dL = tile ? dLB : dLA;
        if (qb + g < SP) {
            pn[(size_t)t * SP + qb + g]       = make_float2(d0[0], d0[1]);
            pn[(size_t)(4 + t) * SP + qb + g] = make_float2(d1[0], d1[1]);
            if (t == 0) pd[qb + g] = dL[0];
        }
        if (qb + 8 + g < SP) {
            pn[(size_t)t * SP + qb + 8 + g]       = make_float2(d0[2], d0[3]);
            pn[(size_t)(4 + t) * SP + qb + 8 + g] = make_float2(d1[2], d1[3]);
            if (t == 0) pd[qb + 8 + g] = dL[2];
        }
    }
}

// ===================================================================
// Combine: add partial halves, divide, emit packed hi/lo g_opk.
// ===================================================================
__global__ void attn_combine(void) {
    int idx = blockIdx.x * 256 + threadIdx.x;     // 64*8*1600 = 819200
    if (idx >= 64 * 8 * SP) return;
    int s = idx % SP;
    int row = idx / SP;        // nh*8 + cp
    int cp = row & 7, nh = row >> 3;
    int n = nh >> 3, h = nh & 7;

    float2 n0 = g_pnum[(size_t)(0 * 64 + nh) * 8 * SP + (size_t)cp * SP + s];
    float2 n1 = g_pnum[(size_t)(1 * 64 + nh) * 8 * SP + (size_t)cp * SP + s];
    float den = g_pden[(size_t)(0 * 64 + nh) * SP + s] +
                g_pden[(size_t)(1 * 64 + nh) * SP + s];
    float inv = 1.f / den;
    g_opk[((size_t)n * 64 + h * 8 + cp) * SP + s] =
        packh2((n0.x + n1.x) * inv, (n0.y + n1.y) * inv);
}

// ===================================================================
extern "C" void kernel_launch(void* const* d_in, const int* in_sizes, int n_in,
                              void* d_out, int out_size) {
    const float* x     = (const float*)d_in[0];
    const float* w_qkv = (const float*)d_in[1];
    const float* w_o   = (const float*)d_in[2];
    const float* b_o   = (const float*)d_in[3];
    float* out = (float*)d_out;

    conv_w<<<(384 * 64 + 255) / 256, 256>>>(w_qkv);
    conv_wo<<<(128 * 64 + 255) / 256, 256>>>(w_o);
    conv_x<<<(NB * 64 * (SP / 4) + 255) / 256, 256>>>(x);
    proj_qkv_mma<<<dim3(SP / 64, 384 / 64, NB), 128>>>();
    attn_mma<<<dim3(13, NB * NHEAD, 2), 128>>>();
    attn_combine<<<(64 * 8 * SP + 255) / 256, 256>>>();
    proj_out_mma<<<dim3(SP / 64, CIN / 64, NB), 128>>>(b_o, out);
}

// round 13
// speedup vs baseline: 1.2647x; 1.2295x over previous
#include <cuda_runtime.h>
#include <cuda_fp16.h>
#include <cstdint>

#define NB    8
#define CIN   128
#define SP    1600
#define NHEAD 8
#define HD    16

typedef unsigned long long u64;

#define ONESH2 0x3C003C00u   // f16x2 (1.0, 1.0)

// f16x2 word: first arg -> low 16 bits, second -> high 16 bits
__device__ __forceinline__ uint32_t f16x2_of(float lo, float hi) {
    uint32_t r;
    asm("cvt.rn.f16x2.f32 %0, %1, %2;" : "=r"(r) : "f"(hi), "f"(lo));
    return r;
}
__device__ __forceinline__ void f16x2_to_f32(uint32_t w, float& lo, float& hi) {
    asm("{ .reg .b16 l, h; mov.b32 {l, h}, %2; cvt.f32.f16 %0, l; cvt.f32.f16 %1, h; }"
        : "=f"(lo), "=f"(hi) : "r"(w));
}
__device__ __forceinline__ u64 packh2(float a, float b) {
    uint32_t hw = f16x2_of(a, b);
    float ha, hb;
    f16x2_to_f32(hw, ha, hb);
    uint32_t lw = f16x2_of(a - ha, b - hb);
    return (u64)hw | ((u64)lw << 32);
}
__device__ __forceinline__ uint32_t ex2h2(uint32_t w) {
    uint32_t r; asm("ex2.approx.f16x2 %0, %1;" : "=r"(r) : "r"(w)); return r;
}

// warp mma: D += A(f16 16x16) * B(f16 16x8), f32 accum
__device__ __forceinline__ void mmaf16(float* d, const uint32_t* a, uint32_t b0, uint32_t b1) {
    asm volatile("mma.sync.aligned.m16n8k16.row.col.f32.f16.f16.f32 "
        "{%0,%1,%2,%3},{%4,%5,%6,%7},{%8,%9},{%0,%1,%2,%3};"
        : "+f"(d[0]), "+f"(d[1]), "+f"(d[2]), "+f"(d[3])
        : "r"(a[0]), "r"(a[1]), "r"(a[2]), "r"(a[3]), "r"(b0), "r"(b1));
}

// Scratch:
__device__ uint2     g_wp[(size_t)384 * 8 * 4];          // W_qkv f16 frags [o][ks][t]
__device__ uint2     g_wop[(size_t)128 * 8 * 4];         // W_o   f16 frags [o][ks][t]
__device__ ulonglong2 g_xp[(size_t)NB * SP * 8 * 4];     // X hi/lo frags [n][tok][ks][t]
__device__ ulonglong2 g_op[(size_t)NB * SP * 8 * 4];     // attn-out hi/lo frags [n][tok][ks=h][t]
__device__ uint32_t  g_qpk[(size_t)64 * 8 * SP + 64];    // Q f16x2 [nh][dpair][s]
__device__ u64       g_kp2[(size_t)64 * SP * 4];         // K frag words [nh][tok][4]
__device__ u64       g_vp2[(size_t)64 * 100 * 16 * 4];   // V frag words [nh][kt][dim][4]
__device__ float2    g_pnum[(size_t)2 * 64 * 8 * SP];    // partial numerators [z][nh][cp][s]
__device__ float     g_pden[(size_t)2 * 64 * SP];        // partial denominators [z][nh][s]

// ===================================================================
// Conversion kernels
// ===================================================================
__global__ void conv_w2(const float* __restrict__ W, uint2* __restrict__ dst, int O) {
    int idx = blockIdx.x * 256 + threadIdx.x;     // (o, ks)
    if (idx >= O * 8) return;
    int ks = idx & 7, o = idx >> 3;
    const float* wr = W + (size_t)o * CIN + 16 * ks;
    uint2 out[4];
    #pragma unroll
    for (int t = 0; t < 4; t++) {
        out[t].x = f16x2_of(wr[2 * t],     wr[2 * t + 1]);
        out[t].y = f16x2_of(wr[2 * t + 8], wr[2 * t + 9]);
    }
    uint2* d = dst + (size_t)idx * 4;
    d[0] = out[0]; d[1] = out[1]; d[2] = out[2]; d[3] = out[3];
}

__global__ void conv_x(const float* __restrict__ X) {
    int idx = blockIdx.x * 256 + threadIdx.x;     // (n, ks, s)
    if (idx >= NB * 8 * SP) return;
    int s = idx % SP;
    int rest = idx / SP;
    int ks = rest & 7, n = rest >> 3;
    const float* xb = X + ((size_t)n * CIN + 16 * ks) * SP + s;
    ulonglong2 out[4];
    #pragma unroll
    for (int t = 0; t < 4; t++) {
        out[t].x = packh2(xb[(size_t)(2 * t) * SP],     xb[(size_t)(2 * t + 1) * SP]);
        out[t].y = packh2(xb[(size_t)(2 * t + 8) * SP], xb[(size_t)(2 * t + 9) * SP]);
    }
    ulonglong2* d = g_xp + ((size_t)(n * SP + s) * 8 + ks) * 4;
    d[0] = out[0]; d[1] = out[1]; d[2] = out[2]; d[3] = out[3];
}

// ===================================================================
// QKV projection: 2-term fp16 mma + pack epilogue.
// ===================================================================
__global__ __launch_bounds__(128) void proj_qkv_mma(void) {
    __shared__ float Ys[64][68];

    const int n  = blockIdx.z;
    const int s0 = blockIdx.x * 64;
    const int o0 = blockIdx.y * 64;
    const int tid = threadIdx.x;
    const int warp = tid >> 5, lane = tid & 31;
    const int g = lane >> 2, t = lane & 3;

    float d[8][4];
    #pragma unroll
    for (int nb = 0; nb < 8; nb++)
        #pragma unroll
        for (int j = 0; j < 4; j++) d[nb][j] = 0.f;

    const int r1 = o0 + warp * 16 + g;
    const int r2 = r1 + 8;

    #pragma unroll
    for (int ks = 0; ks < 8; ks++) {
        uint2 wa = g_wp[((size_t)r1 * 8 + ks) * 4 + t];
        uint2 wb = g_wp[((size_t)r2 * 8 + ks) * 4 + t];
        uint32_t ah[4] = {wa.x, wb.x, wa.y, wb.y};

        const ulonglong2* xq = g_xp + ((size_t)(n * SP + s0 + g) * 8 + ks) * 4 + t;
        #pragma unroll
        for (int nb = 0; nb < 8; nb++) {
            ulonglong2 xv = xq[(size_t)nb * 256];
            mmaf16(d[nb], ah, (uint32_t)xv.x, (uint32_t)xv.y);
            mmaf16(d[nb], ah, (uint32_t)(xv.x >> 32), (uint32_t)(xv.y >> 32));
        }
    }

    #pragma unroll
    for (int nb = 0; nb < 8; nb++) {
        int ol = warp * 16;
        int sl = nb * 8 + 2 * t;
        Ys[ol + g][sl]     = d[nb][0];
        Ys[ol + g][sl + 1] = d[nb][1];
        Ys[ol + 8 + g][sl]     = d[nb][2];
        Ys[ol + 8 + g][sl + 1] = d[nb][3];
    }
    __syncthreads();

    // ---- pack epilogue: 128 threads, 4 o-pairs each ----
    const int tx = tid & 15, ty = tid >> 4;   // ty in 0..7
    const float qs = 0.25f * 1.4426950408889634f;

    #pragma unroll
    for (int p = 0; p < 4; p++) {
        int olo = ty * 8 + 2 * p;
        int o = o0 + olo;
        int hh = o / 48;
        int within = o - hh * 48;
        int nhI = n * 8 + hh;
        float r0[4], r1[4];
        #pragma unroll
        for (int j = 0; j < 4; j++) {
            r0[j] = Ys[olo][tx * 4 + j];
            r1[j] = Ys[olo + 1][tx * 4 + j];
        }
        int tok0 = s0 + tx * 4;
        if (within < 16) {
            int dp = within >> 1;
            uint32_t* dst = g_qpk + ((size_t)nhI * 8 + dp) * SP + tok0;
            #pragma unroll
            for (int j = 0; j < 4; j++)
                dst[j] = f16x2_of(r0[j] * qs, r1[j] * qs);
        } else if (within < 32) {
            int dp = (within - 16) >> 1;
            uint32_t* kb = (uint32_t*)g_kp2 + (size_t)nhI * SP * 8;
            int off = (dp & 3) * 2 + (dp >> 2);
            #pragma unroll
            for (int j = 0; j < 4; j++)
                kb[(size_t)(tok0 + j) * 8 + off] = f16x2_of(r0[j], r1[j]);
        } else {
            int dl = within - 32;
            uint32_t* vb = (uint32_t*)g_vp2 + (size_t)nhI * 100 * 128;
            int kt  = tok0 >> 4;
            int kpl = (tok0 >> 1) & 7;
            size_t base = (size_t)kt * 128;
            vb[base + ((size_t)dl * 4 + (kpl & 3)) * 2 + (kpl >> 2)]             = f16x2_of(r0[0], r0[1]);
            vb[base + ((size_t)dl * 4 + ((kpl + 1) & 3)) * 2 + ((kpl + 1) >> 2)] = f16x2_of(r0[2], r0[3]);
            vb[base + ((size_t)(dl + 1) * 4 + (kpl & 3)) * 2 + (kpl >> 2)]             = f16x2_of(r1[0], r1[1]);
            vb[base + ((size_t)(dl + 1) * 4 + ((kpl + 1) & 3)) * 2 + ((kpl + 1) >> 2)] = f16x2_of(r1[2], r1[3]);
        }
    }
}

// ===================================================================
// Output projection: 2-term fp16 mma + bias epilogue.
// ===================================================================
__global__ __launch_bounds__(128) void proj_out_mma(const float* __restrict__ bias,
                                                    float* __restrict__ Y) {
    __shared__ float Ys[64][68];

    const int n  = blockIdx.z;
    const int s0 = blockIdx.x * 64;
    const int o0 = blockIdx.y * 64;
    const int tid = threadIdx.x;
    const int warp = tid >> 5, lane = tid & 31;
    const int g = lane >> 2, t = lane & 3;

    float d[8][4];
    #pragma unroll
    for (int nb = 0; nb < 8; nb++)
        #pragma unroll
        for (int j = 0; j < 4; j++) d[nb][j] = 0.f;

    const int r1 = o0 + warp * 16 + g;
    const int r2 = r1 + 8;

    #pragma unroll
    for (int ks = 0; ks < 8; ks++) {
        uint2 wa = g_wop[((size_t)r1 * 8 + ks) * 4 + t];
        uint2 wb = g_wop[((size_t)r2 * 8 + ks) * 4 + t];
        uint32_t ah[4] = {wa.x, wb.x, wa.y, wb.y};

        const ulonglong2* xq = g_op + ((size_t)(n * SP + s0 + g) * 8 + ks) * 4 + t;
        #pragma unroll
        for (int nb = 0; nb < 8; nb++) {
            ulonglong2 xv = xq[(size_t)nb * 256];
            mmaf16(d[nb], ah, (uint32_t)xv.x, (uint32_t)xv.y);
            mmaf16(d[nb], ah, (uint32_t)(xv.x >> 32), (uint32_t)(xv.y >> 32));
        }
    }

    #pragma unroll
    for (int nb = 0; nb < 8; nb++) {
        int ol = warp * 16;
        int sl = nb * 8 + 2 * t;
        Ys[ol + g][sl]     = d[nb][0];
        Ys[ol + g][sl + 1] = d[nb][1];
        Ys[ol + 8 + g][sl]     = d[nb][2];
        Ys[ol + 8 + g][sl + 1] = d[nb][3];
    }
    __syncthreads();

    const int tx = tid & 15, ty = tid >> 4;
    #pragma unroll
    for (int r = 0; r < 8; r++) {
        int olo = ty * 8 + r;
        int o = o0 + olo;
        float b = bias[o];
        float4 v = *(const float4*)&Ys[olo][tx * 4];
        v.x += b; v.y += b; v.z += b; v.w += b;
        *(float4*)(Y + ((size_t)n * CIN + o) * SP + s0 + tx * 4) = v;
    }
}

// ===================================================================
// Attention, key-split over blockIdx.z (50 key tiles each half).
// ===================================================================
__global__ __launch_bounds__(128) void attn_mma(void) {
    const int tid  = threadIdx.x;
    const int warp = tid >> 5, lane = tid & 31;
    const int g = lane >> 2, t = lane & 3;
    const int nh = blockIdx.y;
    const int z  = blockIdx.z;
    const int q0 = blockIdx.x * 128 + warp * 32;

    const uint32_t* qp = g_qpk + (size_t)nh * 8 * SP;
    const u64* kp2 = g_kp2 + (size_t)nh * SP * 4;
    const u64* vp2 = g_vp2 + (size_t)nh * 100 * 64;

    uint32_t aq0[4], aq1[4];
    {
        const uint32_t* q1 = qp + (size_t)t * SP;
        const uint32_t* q2 = qp + (size_t)(t + 4) * SP;
        aq0[0] = q1[q0 + g];      aq0[1] = q1[q0 + 8 + g];
        aq0[2] = q2[q0 + g];      aq0[3] = q2[q0 + 8 + g];
        aq1[0] = q1[q0 + 16 + g]; aq1[1] = q1[q0 + 24 + g];
        aq1[2] = q2[q0 + 16 + g]; aq1[3] = q2[q0 + 24 + g];
    }

    float dA0[4] = {0,0,0,0}, dA1[4] = {0,0,0,0};
    float dB0[4] = {0,0,0,0}, dB1[4] = {0,0,0,0};
    float dLA[4] = {0,0,0,0}, dLB[4] = {0,0,0,0};

    const u64* kA_p = kp2 + (size_t)g * 4 + t;
    const u64* kB_p = kp2 + (size_t)(8 + g) * 4 + t;
    const u64* vA_p = vp2 + (size_t)g * 4 + t;
    const u64* vB_p = vp2 + (size_t)(8 + g) * 4 + t;

    const int kt0 = z * 50, kt1 = kt0 + 50;

    #pragma unroll 2
    for (int kt = kt0; kt < kt1; kt++) {
        u64 kA = kA_p[(size_t)kt * 64];
        u64 kB = kB_p[(size_t)kt * 64];

        float s00[4] = {0,0,0,0}, s01[4] = {0,0,0,0};
        float s10[4] = {0,0,0,0}, s11[4] = {0,0,0,0};
        mmaf16(s00, aq0, (uint32_t)kA, (uint32_t)(kA >> 32));
        mmaf16(s01, aq0, (uint32_t)kB, (uint32_t)(kB >> 32));
        mmaf16(s10, aq1, (uint32_t)kA, (uint32_t)(kA >> 32));
        mmaf16(s11, aq1, (uint32_t)kB, (uint32_t)(kB >> 32));

        uint32_t paA[4], paB[4];
        paA[0] = ex2h2(f16x2_of(s00[0], s00[1]));
        paA[1] = ex2h2(f16x2_of(s00[2], s00[3]));
        paA[2] = ex2h2(f16x2_of(s01[0], s01[1]));
        paA[3] = ex2h2(f16x2_of(s01[2], s01[3]));
        paB[0] = ex2h2(f16x2_of(s10[0], s10[1]));
        paB[1] = ex2h2(f16x2_of(s10[2], s10[3]));
        paB[2] = ex2h2(f16x2_of(s11[0], s11[1]));
        paB[3] = ex2h2(f16x2_of(s11[2], s11[3]));

        mmaf16(dLA, paA, ONESH2, ONESH2);
        mmaf16(dLB, paB, ONESH2, ONESH2);

        u64 vA = vA_p[(size_t)kt * 64];
        u64 vB = vB_p[(size_t)kt * 64];
        mmaf16(dA0, paA, (uint32_t)vA, (uint32_t)(vA >> 32));
        mmaf16(dA1, paA, (uint32_t)vB, (uint32_t)(vB >> 32));
        mmaf16(dB0, paB, (uint32_t)vA, (uint32_t)(vA >> 32));
        mmaf16(dB1, paB, (uint32_t)vB, (uint32_t)(vB >> 32));
    }

    float2* pn = g_pnum + ((size_t)(z * 64 + nh) * 8) * SP;
    float*  pd = g_pden + (size_t)(z * 64 + nh) * SP;

    #pragma unroll
    for (int tile = 0; tile < 2; tile++) {
        int qb = q0 + tile * 16;
        const float* d0 = tile ? dB0 : dA0;
        const float* d1 = tile ? dB1 : dA1;
        const float* dL = tile ? dLB : dLA;
        if (qb + g < SP) {
            pn[(size_t)t * SP + qb + g]       = make_float2(d0[0], d0[1]);
            pn[(size_t)(4 + t) * SP + qb + g] = make_float2(d1[0], d1[1]);
            if (t == 0) pd[qb + g] = dL[0];
        }
        if (qb + 8 + g < SP) {
            pn[(size_t)t * SP + qb + 8 + g]       = make_float2(d0[2], d0[3]);
            pn[(size_t)(4 + t) * SP + qb + 8 + g] = make_float2(d1[2], d1[3]);
            if (t == 0) pd[qb + 8 + g] = dL[2];
        }
    }
}

// ===================================================================
// Combine: add halves, divide, emit fragment-ready hi/lo g_op.
// Thread = (nh, s); writes 64B contiguous.
// ===================================================================
__global__ void attn_combine(void) {
    int idx = blockIdx.x * 256 + threadIdx.x;     // 64*1600 = 102400
    if (idx >= 64 * SP) return;
    int s = idx % SP;
    int nh = idx / SP;
    int n = nh >> 3, h = nh & 7;

    const float2* pn0 = g_pnum + (size_t)nh * 8 * SP;
    const float2* pn1 = g_pnum + (size_t)(64 + nh) * 8 * SP;
    float den = g_pden[(size_t)nh * SP + s] + g_pden[(size_t)(64 + nh) * SP + s];
    float inv = 1.f / den;

    ulonglong2 out[4];
    #pragma unroll
    for (int t = 0; t < 4; t++) {
        float2 a0 = pn0[(size_t)t * SP + s];
        float2 b0 = pn1[(size_t)t * SP + s];
        float2 a1 = pn0[(size_t)(4 + t) * SP + s];
        float2 b1 = pn1[(size_t)(4 + t) * SP + s];
        out[t].x = packh2((a0.x + b0.x) * inv, (a0.y + b0.y) * inv);
        out[t].y = packh2((a1.x + b1.x) * inv, (a1.y + b1.y) * inv);
    }
    ulonglong2* d = g_op + ((size_t)(n * SP + s) * 8 + h) * 4;
    d[0] = out[0]; d[1] = out[1]; d[2] = out[2]; d[3] = out[3];
}

// ===================================================================
extern "C" void kernel_launch(void* const* d_in, const int* in_sizes, int n_in,
                              void* d_out, int out_size) {
    const float* x     = (const float*)d_in[0];
    const float* w_qkv = (const float*)d_in[1];
    const float* w_o   = (const float*)d_in[2];
    const float* b_o   = (const float*)d_in[3];
    float* out = (float*)d_out;

    uint2 *wp_ptr, *wop_ptr;
    cudaGetSymbolAddress((void**)&wp_ptr, g_wp);
    cudaGetSymbolAddress((void**)&wop_ptr, g_wop);

    conv_w2<<<(384 * 8 + 255) / 256, 256>>>(w_qkv, wp_ptr, 384);
    conv_w2<<<(128 * 8 + 255) / 256, 256>>>(w_o, wop_ptr, 128);
    conv_x<<<(NB * 8 * SP + 255) / 256, 256>>>(x);
    proj_qkv_mma<<<dim3(SP / 64, 384 / 64, NB), 128>>>();
    attn_mma<<<dim3(13, NB * NHEAD, 2), 128>>>();
    attn_combine<<<(64 * SP + 255) / 256, 256>>>();
    proj_out_mma<<<dim3(SP / 64, CIN / 64, NB), 128>>>(b_o, out);
}